// round 2
// baseline (speedup 1.0000x reference)
#include <cuda_runtime.h>
#include <math.h>

#define NSEQ  256      // B*S
#define TLEN  128
#define EMBED 512
#define UNITS 512
#define GDIM  2048     // 4*UNITS
#define NROWS 32768    // NSEQ*TLEN

// Scratch (allocation-free rule: __device__ globals)
__device__ float g_xW[2ull * NROWS * GDIM];      // [dir][m*T+t][4U]  512 MB
__device__ float g_h[2][2][NSEQ][UNITS];         // [parity][dir][n][u]
__device__ float g_c[2][NSEQ][UNITS];            // [dir][n][u]

__device__ __forceinline__ float sigmoidf_(float v) {
    return 1.0f / (1.0f + expf(-v));
}

// ---------------------------------------------------------------------------
// Zero h(parity 0) and c each replay (deterministic).
// ---------------------------------------------------------------------------
__global__ void init_state_kernel() {
    int i = blockIdx.x * blockDim.x + threadIdx.x;
    if (i < 2 * NSEQ * UNITS) {
        ((float*)g_h)[i] = 0.0f;   // first 2*NSEQ*UNITS floats == parity-0 slice
        ((float*)g_c)[i] = 0.0f;
    }
}

// ---------------------------------------------------------------------------
// Fused embedding-gather + input projection GEMM (+bias).
// C[dir][m][j] = emb_table[id(dir,m)] . W_dir[:,j] + b_dir[j]
// Tile: BM=128 x BN=64, BK=16. 256 threads, 8x4 outputs each.
// grid = (GDIM/64, NROWS/128, 2)
// ---------------------------------------------------------------------------
__global__ __launch_bounds__(256) void proj_kernel(
    const int*   __restrict__ x,
    const float* __restrict__ emb,
    const float* __restrict__ W_f, const float* __restrict__ b_f,
    const float* __restrict__ W_b, const float* __restrict__ b_b)
{
    const int dir  = blockIdx.z;
    const int row0 = blockIdx.y * 128;
    const int col0 = blockIdx.x * 64;
    const float* __restrict__ W    = dir ? W_b : W_f;
    const float* __restrict__ bias = dir ? b_b : b_f;

    __shared__ float a_s[16][132];
    __shared__ float u_s[16][68];
    __shared__ int   ids_s[128];

    const int tid = threadIdx.x;
    const int tx  = tid & 15;
    const int ty  = tid >> 4;

    if (tid < 128) {
        int m  = row0 + tid;
        int n  = m >> 7;
        int t  = m & 127;
        int tt = dir ? (TLEN - 1 - t) : t;
        ids_s[tid] = x[(n << 7) + tt];
    }
    __syncthreads();

    float acc[8][4];
    #pragma unroll
    for (int i = 0; i < 8; i++)
        #pragma unroll
        for (int j = 0; j < 4; j++) acc[i][j] = 0.0f;

    const int ar = tid >> 1;          // 0..127 (row within tile)
    const int ak = (tid & 1) * 8;     // 0 or 8
    const int uk = tid >> 4;          // 0..15
    const int uc = (tid & 15) * 4;    // 0..60

    for (int k0 = 0; k0 < EMBED; k0 += 16) {
        // --- A tile (gathered embedding rows), stored transposed ---
        const float* arow = emb + (size_t)ids_s[ar] * EMBED + k0 + ak;
        float4 av0 = *(const float4*)(arow);
        float4 av1 = *(const float4*)(arow + 4);
        a_s[ak + 0][ar] = av0.x; a_s[ak + 1][ar] = av0.y;
        a_s[ak + 2][ar] = av0.z; a_s[ak + 3][ar] = av0.w;
        a_s[ak + 4][ar] = av1.x; a_s[ak + 5][ar] = av1.y;
        a_s[ak + 6][ar] = av1.z; a_s[ak + 7][ar] = av1.w;
        // --- W tile ---
        *(float4*)&u_s[uk][uc] =
            *(const float4*)(W + (size_t)(k0 + uk) * GDIM + col0 + uc);
        __syncthreads();

        #pragma unroll
        for (int kk = 0; kk < 16; kk++) {
            float4 a0 = *(const float4*)&a_s[kk][ty * 8];
            float4 a1 = *(const float4*)&a_s[kk][ty * 8 + 4];
            float4 b0 = *(const float4*)&u_s[kk][tx * 4];
            float av[8] = {a0.x, a0.y, a0.z, a0.w, a1.x, a1.y, a1.z, a1.w};
            float bv[4] = {b0.x, b0.y, b0.z, b0.w};
            #pragma unroll
            for (int i = 0; i < 8; i++)
                #pragma unroll
                for (int j = 0; j < 4; j++)
                    acc[i][j] += av[i] * bv[j];
        }
        __syncthreads();
    }

    float4 bvv = *(const float4*)(bias + col0 + tx * 4);
    float* outp = g_xW + (size_t)dir * NROWS * GDIM;
    #pragma unroll
    for (int i = 0; i < 8; i++) {
        int m = row0 + ty * 8 + i;
        float4 v;
        v.x = acc[i][0] + bvv.x;
        v.y = acc[i][1] + bvv.y;
        v.z = acc[i][2] + bvv.z;
        v.w = acc[i][3] + bvv.w;
        *(float4*)(outp + (size_t)m * GDIM + col0 + tx * 4) = v;
    }
}

// ---------------------------------------------------------------------------
// One LSTM timestep, both directions. z = h@U + xW[t]; gates; masked update.
// Block: 64 sequences x 32 units (x 4 gates = 128 cols). 256 threads, 4x8 each.
// grid = (NSEQ/64, UNITS/32, 2) = (4,16,2) = 128 blocks.
// Local col c: gate = c>>5, ul = c&31 -> global col j = gate*512 + u0 + ul.
// ---------------------------------------------------------------------------
__global__ __launch_bounds__(256) void step_kernel(
    const int*   __restrict__ x,
    const float* __restrict__ U_f,
    const float* __restrict__ U_b,
    int t, int par)
{
    const int dir = blockIdx.z;
    const int m0  = blockIdx.x * 64;
    const int u0  = blockIdx.y * 32;
    const float* __restrict__ U = dir ? U_b : U_f;

    __shared__ float h_s[16][68];
    __shared__ float u_s[16][132];
    __shared__ float z_s[64][132];

    const int tid = threadIdx.x;
    const int tx  = tid & 15;
    const int ty  = tid >> 4;

    float acc[4][8];
    #pragma unroll
    for (int i = 0; i < 4; i++)
        #pragma unroll
        for (int j = 0; j < 8; j++) acc[i][j] = 0.0f;

    const int hr = tid >> 2;          // 0..63
    const int hk = (tid & 3) * 4;     // 0,4,8,12
    const int uk = tid >> 4;          // 0..15
    const int uc = (tid & 15) * 4;    // 0..60

    const float* __restrict__ hbase = &g_h[par][dir][0][0];

    for (int k0 = 0; k0 < UNITS; k0 += 16) {
        // h tile, transposed
        float4 hv = *(const float4*)(hbase + (size_t)(m0 + hr) * UNITS + k0 + hk);
        h_s[hk + 0][hr] = hv.x;
        h_s[hk + 1][hr] = hv.y;
        h_s[hk + 2][hr] = hv.z;
        h_s[hk + 3][hr] = hv.w;
        // U tile: two 64-col halves (gate-major local layout)
        {
            int c = uc;                       // gates 0,1
            int gate = c >> 5, ul = c & 31;
            *(float4*)&u_s[uk][c] =
                *(const float4*)(U + (size_t)(k0 + uk) * GDIM + gate * 512 + u0 + ul);
        }
        {
            int c = 64 + uc;                  // gates 2,3
            int gate = c >> 5, ul = c & 31;
            *(float4*)&u_s[uk][c] =
                *(const float4*)(U + (size_t)(k0 + uk) * GDIM + gate * 512 + u0 + ul);
        }
        __syncthreads();

        #pragma unroll
        for (int kk = 0; kk < 16; kk++) {
            float4 a  = *(const float4*)&h_s[kk][ty * 4];
            float4 b0 = *(const float4*)&u_s[kk][tx * 4];
            float4 b1 = *(const float4*)&u_s[kk][64 + tx * 4];
            float av[4] = {a.x, a.y, a.z, a.w};
            float bv[8] = {b0.x, b0.y, b0.z, b0.w, b1.x, b1.y, b1.z, b1.w};
            #pragma unroll
            for (int i = 0; i < 4; i++)
                #pragma unroll
                for (int j = 0; j < 8; j++)
                    acc[i][j] += av[i] * bv[j];
        }
        __syncthreads();
    }

    // z = acc + xW[dir][m][t][:] -> z_s
    const float* __restrict__ xw = g_xW + (size_t)dir * NROWS * GDIM;
    #pragma unroll
    for (int i = 0; i < 4; i++) {
        int m = m0 + ty * 4 + i;
        size_t rowbase = ((size_t)m * TLEN + t) * GDIM;
        {
            int c = tx * 4; int gate = c >> 5, ul = c & 31;
            float4 v = *(const float4*)(xw + rowbase + gate * 512 + u0 + ul);
            v.x += acc[i][0]; v.y += acc[i][1]; v.z += acc[i][2]; v.w += acc[i][3];
            *(float4*)&z_s[ty * 4 + i][c] = v;
        }
        {
            int c = 64 + tx * 4; int gate = c >> 5, ul = c & 31;
            float4 v = *(const float4*)(xw + rowbase + gate * 512 + u0 + ul);
            v.x += acc[i][4]; v.y += acc[i][5]; v.z += acc[i][6]; v.w += acc[i][7];
            *(float4*)&z_s[ty * 4 + i][c] = v;
        }
    }
    __syncthreads();

    // Gate math + masked state update. thread -> row r, 8 units.
    const int r   = tid >> 2;           // 0..63
    const int ul0 = (tid & 3) * 8;      // 0,8,16,24
    const int m   = m0 + r;
    const int tt  = dir ? (TLEN - 1 - t) : t;
    const bool mv = (x[(m << 7) + tt] != 0);

    float*       cptr  = &g_c[dir][m][u0];
    const float* hprev = &g_h[par][dir][m][u0];
    float*       hout  = &g_h[par ^ 1][dir][m][u0];

    #pragma unroll
    for (int j = 0; j < 8; j++) {
        int ul = ul0 + j;
        float zi = z_s[r][ul];
        float zf = z_s[r][32 + ul];
        float zg = z_s[r][64 + ul];
        float zo = z_s[r][96 + ul];
        float ig = sigmoidf_(zi);
        float fg = sigmoidf_(zf);
        float gg = tanhf(zg);
        float og = sigmoidf_(zo);
        float cold = cptr[ul];
        float cn = fg * cold + ig * gg;
        float hn = og * tanhf(cn);
        cptr[ul] = mv ? cn : cold;
        hout[ul] = mv ? hn : hprev[ul];
    }
}

// ---------------------------------------------------------------------------
// Pack final hidden states: out[n][0:512]=h_fwd, out[n][512:1024]=h_bwd.
// After 128 steps the final state lives in parity 0.
// ---------------------------------------------------------------------------
__global__ void finalize_kernel(float* __restrict__ out) {
    int i = blockIdx.x * blockDim.x + threadIdx.x;
    if (i < NSEQ * 1024) {
        int n   = i >> 10;
        int j   = i & 1023;
        int dir = j >> 9;
        int u   = j & 511;
        out[i] = g_h[0][dir][n][u];
    }
}

// ---------------------------------------------------------------------------
extern "C" void kernel_launch(void* const* d_in, const int* in_sizes, int n_in,
                              void* d_out, int out_size)
{
    const int*   x    = (const int*)  d_in[0];
    const float* emb  = (const float*)d_in[1];
    const float* W_f  = (const float*)d_in[2];
    const float* U_f  = (const float*)d_in[3];
    const float* b_f  = (const float*)d_in[4];
    const float* W_b  = (const float*)d_in[5];
    const float* U_b  = (const float*)d_in[6];
    const float* b_b  = (const float*)d_in[7];
    float* out = (float*)d_out;

    init_state_kernel<<<512, 512>>>();

    proj_kernel<<<dim3(GDIM / 64, NROWS / 128, 2), 256>>>(x, emb, W_f, b_f, W_b, b_b);

    for (int t = 0; t < TLEN; t++) {
        step_kernel<<<dim3(NSEQ / 64, UNITS / 32, 2), 256>>>(x, U_f, U_b, t, t & 1);
    }

    finalize_kernel<<<512, 512>>>(out);
}

// round 4
// speedup vs baseline: 1.7988x; 1.7988x over previous
#include <cuda_runtime.h>
#include <cstdint>
#include <math.h>

#define NSEQ  256      // B*S
#define TLEN  128
#define EMBED 512
#define UNITS 512
#define GDIM  2048     // 4*UNITS
#define NROWS 32768    // NSEQ*TLEN
#define NBLK  128      // persistent CTAs (all co-resident, 1/SM)

// Scratch (allocation-free rule: __device__ globals)
__device__ float g_xW[2ull * NROWS * GDIM];      // [dir][n*T+t][4U]
__device__ float g_h[2][2][NSEQ][UNITS];         // [parity][dir][n][u]
__device__ unsigned g_bar_count = 0;
__device__ volatile unsigned g_bar_gen = 0;

// ---------------------------------------------------------------------------
// tf32 helpers (legacy mma.sync path — tcgen05 unavailable: toolchain targets
// base sm_103, no 'a' features)
// ---------------------------------------------------------------------------
__device__ __forceinline__ uint32_t f2tf(float f) {
    uint32_t r;
    asm("cvt.rna.tf32.f32 %0, %1;" : "=r"(r) : "f"(f));
    return r;
}

// D(16x8) += A(16x8,row) * B(8x8,col). tf32 in, f32 acc.
__device__ __forceinline__ void mma8(float* d, const uint32_t* a,
                                     uint32_t b0, uint32_t b1) {
    asm volatile(
        "mma.sync.aligned.m16n8k8.row.col.f32.tf32.tf32.f32 "
        "{%0,%1,%2,%3}, {%4,%5,%6,%7}, {%8,%9}, {%0,%1,%2,%3};"
        : "+f"(d[0]), "+f"(d[1]), "+f"(d[2]), "+f"(d[3])
        : "r"(a[0]), "r"(a[1]), "r"(a[2]), "r"(a[3]), "r"(b0), "r"(b1));
}

__device__ __forceinline__ float fsig(float x)   { return 1.0f / (1.0f + __expf(-x)); }
__device__ __forceinline__ float ftanh_(float x) { return 1.0f - 2.0f / (__expf(2.0f * x) + 1.0f); }

__device__ __forceinline__ void grid_sync() {
    __threadfence();
    __syncthreads();
    if (threadIdx.x == 0) {
        unsigned gen = g_bar_gen;
        if (atomicAdd(&g_bar_count, 1u) == NBLK - 1) {
            g_bar_count = 0;
            __threadfence();
            g_bar_gen = gen + 1;
        } else {
            while (g_bar_gen == gen) __nanosleep(32);
            __threadfence();
        }
    }
    __syncthreads();
}

// ===========================================================================
// Tensorized proj: g_xW[dir][m][:] = emb[id(dir,m)] @ W_dir + b_dir
// CTA tile: M=128 (gathered rows) x N=128, K=512 in 8 chunks of 64.
// 128 threads = 4 warps in 2x2; warp tile 64x64 (4 M-tiles x 8 N-tiles).
// SMEM: A(tf32) 128x68 u32 = 34816B; B(tf32 packed) [8ks][128n][4kk][2] =
// 32768B; Z(f32, stride 132) overlays A+B (exactly 67584B); ids 512B.
// ===========================================================================
#define PJ_AS   0
#define PJ_BS   34816
#define PJ_IDS  67584
#define PJ_SMEM 68096

__global__ __launch_bounds__(128) void proj_kernel(
    const int*   __restrict__ x,
    const float* __restrict__ emb,
    const float* __restrict__ W_f, const float* __restrict__ b_f,
    const float* __restrict__ W_b, const float* __restrict__ b_b)
{
    extern __shared__ char smem[];
    uint32_t* As  = (uint32_t*)(smem + PJ_AS);    // stride 68
    uint32_t* Bs  = (uint32_t*)(smem + PJ_BS);
    float*    Zs  = (float*)smem;                 // stride 132 (overlay)
    int*      ids = (int*)(smem + PJ_IDS);

    const int tid  = threadIdx.x;
    const int lane = tid & 31;
    const int wid  = tid >> 5;
    const int wr   = wid >> 1;       // warp row (0..1) -> 64 rows
    const int wc   = wid & 1;        // warp col (0..1) -> 64 cols
    const int n0   = blockIdx.x * 128;
    const int row0 = blockIdx.y * 128;
    const int dir  = blockIdx.z;
    const float* __restrict__ W    = dir ? W_b : W_f;
    const float* __restrict__ bias = dir ? b_b : b_f;

    // gather ids for the 128 rows of this tile
    {
        int m  = row0 + tid;
        int n  = m >> 7;
        int t  = m & 127;
        int tt = dir ? (TLEN - 1 - t) : t;
        ids[tid] = x[(n << 7) + tt];
    }
    __syncthreads();

    float acc[4][8][4];
    #pragma unroll
    for (int a = 0; a < 4; a++)
        #pragma unroll
        for (int b = 0; b < 8; b++)
            #pragma unroll
            for (int c = 0; c < 4; c++) acc[a][b][c] = 0.0f;

    const float* arow = emb + (size_t)ids[tid] * EMBED;

    for (int cc = 0; cc < 8; cc++) {
        // ---- stage A: row tid, 64 k-values, cvt to tf32 ----
        #pragma unroll
        for (int i = 0; i < 16; i++) {
            float4 v = __ldg((const float4*)(arow + cc * 64 + i * 4));
            uint4 w;
            w.x = f2tf(v.x); w.y = f2tf(v.y); w.z = f2tf(v.z); w.w = f2tf(v.w);
            *(uint4*)&As[tid * 68 + i * 4] = w;
        }
        // ---- stage B: 64k x 128n, packed (k,k+4) pairs ----
        #pragma unroll
        for (int it = 0; it < 16; it++) {
            int idx4 = tid + it * 128;         // 0..2047 float4s
            int kl   = idx4 >> 5;              // 0..63
            int n4   = (idx4 & 31) * 4;
            float4 v = __ldg((const float4*)(W + (size_t)(cc * 64 + kl) * GDIM + n0 + n4));
            int base = (kl >> 3) * 128;
            int koff = (kl & 3) * 2 + ((kl >> 2) & 1);
            Bs[(base + n4 + 0) * 8 + koff] = f2tf(v.x);
            Bs[(base + n4 + 1) * 8 + koff] = f2tf(v.y);
            Bs[(base + n4 + 2) * 8 + koff] = f2tf(v.z);
            Bs[(base + n4 + 3) * 8 + koff] = f2tf(v.w);
        }
        __syncthreads();

        #pragma unroll
        for (int j = 0; j < 8; j++) {
            uint32_t afr[4][4];
            const int rb = wr * 64 + (lane >> 2);
            const int kb = j * 8 + (lane & 3);
            #pragma unroll
            for (int mt = 0; mt < 4; mt++) {
                int r = rb + mt * 16;
                afr[mt][0] = As[r * 68 + kb];
                afr[mt][1] = As[(r + 8) * 68 + kb];
                afr[mt][2] = As[r * 68 + kb + 4];
                afr[mt][3] = As[(r + 8) * 68 + kb + 4];
            }
            #pragma unroll
            for (int nt = 0; nt < 8; nt++) {
                int n = wc * 64 + nt * 8 + (lane >> 2);
                uint2 bb = *(const uint2*)&Bs[(j * 128 + n) * 8 + (lane & 3) * 2];
                #pragma unroll
                for (int mt = 0; mt < 4; mt++)
                    mma8(acc[mt][nt], afr[mt], bb.x, bb.y);
            }
        }
        __syncthreads();
    }

    // ---- fragments -> Z smem (overlay; loop done) ----
    #pragma unroll
    for (int mt = 0; mt < 4; mt++) {
        int r = wr * 64 + mt * 16 + (lane >> 2);
        #pragma unroll
        for (int nt = 0; nt < 8; nt++) {
            int c = wc * 64 + nt * 8 + 2 * (lane & 3);
            *(float2*)&Zs[r * 132 + c]       = make_float2(acc[mt][nt][0], acc[mt][nt][1]);
            *(float2*)&Zs[(r + 8) * 132 + c] = make_float2(acc[mt][nt][2], acc[mt][nt][3]);
        }
    }
    __syncthreads();

    // ---- coalesced write (+bias) ----
    float* orow = g_xW + (size_t)dir * NROWS * GDIM + (size_t)(row0 + tid) * GDIM + n0;
    #pragma unroll
    for (int q = 0; q < 32; q++) {
        float4 v  = *(float4*)&Zs[tid * 132 + q * 4];
        float4 bv = __ldg((const float4*)(bias + n0 + q * 4));
        v.x += bv.x; v.y += bv.y; v.z += bv.z; v.w += bv.w;
        *(float4*)(orow + q * 4) = v;
    }
}

// ===========================================================================
// Persistent tf32 recurrence. Grid (32,2,2)=128 CTAs, 128 threads.
// CTA: 128 seqs x 64 cols (16 units x 4 gates) x dir. U slice tf32-resident.
// Warp w: rows w*32..w*32+31 (2 M-tiles x 8 N-tiles, 64 accum regs).
// SMEM: A 128x68 u32 (34816), B packed [64ks][64n][4][2] (131072),
//       Z f32 stride 72 (36864). Total 202752.
// ===========================================================================
#define RC_AS   0
#define RC_BS   34816
#define RC_ZS   165888
#define RC_SMEM 202752

__global__ __launch_bounds__(128, 1) void lstm_kernel(
    const int*   __restrict__ x,
    const float* __restrict__ U_f,
    const float* __restrict__ U_b,
    float* __restrict__ out)
{
    extern __shared__ char smem[];
    uint32_t* As = (uint32_t*)(smem + RC_AS);    // stride 68
    uint32_t* Bs = (uint32_t*)(smem + RC_BS);
    float*    Zs = (float*)(smem + RC_ZS);       // stride 72

    const int tid  = threadIdx.x;
    const int lane = tid & 31;
    const int wid  = tid >> 5;
    const int u0   = blockIdx.x * 16;
    const int m0   = blockIdx.y * 128;
    const int dir  = blockIdx.z;
    const float* __restrict__ U = dir ? U_b : U_f;
    const int m = m0 + tid;              // this thread's sequence

    // ---- one-time: pack resident B (U slice) as tf32 ----
    // B row n = gate*16+u -> U col (n>>4)*512 + u0 + (n&15); pairs (k,k+4) adj.
    #pragma unroll 4
    for (int it = 0; it < 256; it++) {
        int idx = tid + it * 128;         // 0..32767
        int k = idx >> 6, n = idx & 63;
        float v = U[(size_t)k * GDIM + ((n >> 4) << 9) + u0 + (n & 15)];
        Bs[((k >> 3) * 64 + n) * 8 + (k & 3) * 2 + ((k >> 2) & 1)] = f2tf(v);
    }

    // ---- one-time: mask bits + zero h parity-0 slice ----
    unsigned mbits[4] = {0, 0, 0, 0};
    {
        const int* xr = x + (size_t)m * TLEN;
        for (int t = 0; t < TLEN; t += 4) {
            int4 v = *(const int4*)(xr + t);
            if (v.x) mbits[t >> 5]       |= 1u << (t & 31);
            if (v.y) mbits[(t + 1) >> 5] |= 1u << ((t + 1) & 31);
            if (v.z) mbits[(t + 2) >> 5] |= 1u << ((t + 2) & 31);
            if (v.w) mbits[(t + 3) >> 5] |= 1u << ((t + 3) & 31);
        }
        float4 z4 = make_float4(0.f, 0.f, 0.f, 0.f);
        float4* hp = (float4*)&g_h[0][dir][m][u0];
        __stcg(hp + 0, z4); __stcg(hp + 1, z4); __stcg(hp + 2, z4); __stcg(hp + 3, z4);
    }
    __syncthreads();
    grid_sync();

    float cst[16], hst[16];
    #pragma unroll
    for (int i = 0; i < 16; i++) { cst[i] = 0.f; hst[i] = 0.f; }

    for (int t = 0; t < TLEN; t++) {
        const int par = t & 1;
        const float* __restrict__ hrow = &g_h[par][dir][m0 + tid][0];

        float acc[2][8][4];
        #pragma unroll
        for (int a = 0; a < 2; a++)
            #pragma unroll
            for (int b = 0; b < 8; b++)
                #pragma unroll
                for (int c = 0; c < 4; c++) acc[a][b][c] = 0.0f;

        // prefetch chunk 0 of h
        float4 pf[16];
        #pragma unroll
        for (int i = 0; i < 16; i++)
            pf[i] = __ldcg((const float4*)(hrow) + i);

        float zx[64];

        #pragma unroll 1
        for (int cc = 0; cc < 8; cc++) {
            // stage prefetched chunk -> A smem (cvt tf32)
            #pragma unroll
            for (int i = 0; i < 16; i++) {
                uint4 w;
                w.x = f2tf(pf[i].x); w.y = f2tf(pf[i].y);
                w.z = f2tf(pf[i].z); w.w = f2tf(pf[i].w);
                *(uint4*)&As[tid * 68 + i * 4] = w;
            }
            __syncthreads();

            if (cc < 7) {                 // prefetch next chunk (overlaps mma)
                #pragma unroll
                for (int i = 0; i < 16; i++)
                    pf[i] = __ldcg((const float4*)(hrow + (cc + 1) * 64) + i);
            } else {                      // prefetch xW gate pre-activations
                const float* xw = g_xW + ((size_t)dir * NROWS + (size_t)m * TLEN + t) * GDIM + u0;
                #pragma unroll
                for (int g = 0; g < 4; g++)
                    #pragma unroll
                    for (int q = 0; q < 4; q++) {
                        float4 v = __ldcs((const float4*)(xw + g * 512 + q * 4));
                        zx[g * 16 + q * 4 + 0] = v.x;
                        zx[g * 16 + q * 4 + 1] = v.y;
                        zx[g * 16 + q * 4 + 2] = v.z;
                        zx[g * 16 + q * 4 + 3] = v.w;
                    }
            }

            #pragma unroll
            for (int j = 0; j < 8; j++) {
                uint32_t afr[2][4];
                const int rb = wid * 32 + (lane >> 2);
                const int kb = j * 8 + (lane & 3);
                #pragma unroll
                for (int mt = 0; mt < 2; mt++) {
                    int r = rb + mt * 16;
                    afr[mt][0] = As[r * 68 + kb];
                    afr[mt][1] = As[(r + 8) * 68 + kb];
                    afr[mt][2] = As[r * 68 + kb + 4];
                    afr[mt][3] = As[(r + 8) * 68 + kb + 4];
                }
                const int ks = cc * 8 + j;
                #pragma unroll
                for (int nt = 0; nt < 8; nt++) {
                    int n = nt * 8 + (lane >> 2);
                    uint2 bb = *(const uint2*)&Bs[(ks * 64 + n) * 8 + (lane & 3) * 2];
                    mma8(acc[0][nt], afr[0], bb.x, bb.y);
                    mma8(acc[1][nt], afr[1], bb.x, bb.y);
                }
            }
            __syncthreads();
        }

        // ---- fragments -> Z smem ----
        #pragma unroll
        for (int mt = 0; mt < 2; mt++) {
            int r = wid * 32 + mt * 16 + (lane >> 2);
            #pragma unroll
            for (int nt = 0; nt < 8; nt++) {
                int c = nt * 8 + 2 * (lane & 3);
                *(float2*)&Zs[r * 72 + c]       = make_float2(acc[mt][nt][0], acc[mt][nt][1]);
                *(float2*)&Zs[(r + 8) * 72 + c] = make_float2(acc[mt][nt][2], acc[mt][nt][3]);
            }
        }
        __syncthreads();

        // ---- gate math + masked update (thread = one seq, 16 units) ----
        const int  tt = dir ? (TLEN - 1 - t) : t;
        const bool mv = (mbits[tt >> 5] >> (tt & 31)) & 1;

        #pragma unroll
        for (int u = 0; u < 16; u++) {
            float zi = zx[u]      + Zs[tid * 72 + u];
            float zf = zx[16 + u] + Zs[tid * 72 + 16 + u];
            float zg = zx[32 + u] + Zs[tid * 72 + 32 + u];
            float zo = zx[48 + u] + Zs[tid * 72 + 48 + u];
            float ig = fsig(zi);
            float fg = fsig(zf);
            float gg = ftanh_(zg);
            float og = fsig(zo);
            float cn = fg * cst[u] + ig * gg;
            float hn = og * ftanh_(cn);
            if (mv) { cst[u] = cn; hst[u] = hn; }
        }

        // ---- store h(t+1) ----
        {
            float4* hdst = (float4*)&g_h[par ^ 1][dir][m][u0];
            #pragma unroll
            for (int q = 0; q < 4; q++)
                __stcg(hdst + q, make_float4(hst[q * 4 + 0], hst[q * 4 + 1],
                                             hst[q * 4 + 2], hst[q * 4 + 3]));
        }
        grid_sync();
    }

    // ---- final output ----
    {
        float* op = out + (size_t)m * 1024 + dir * 512 + u0;
        #pragma unroll
        for (int q = 0; q < 4; q++)
            *(float4*)(op + q * 4) = make_float4(hst[q * 4 + 0], hst[q * 4 + 1],
                                                 hst[q * 4 + 2], hst[q * 4 + 3]);
    }
}

// ===========================================================================
extern "C" void kernel_launch(void* const* d_in, const int* in_sizes, int n_in,
                              void* d_out, int out_size)
{
    const int*   x    = (const int*)  d_in[0];
    const float* emb  = (const float*)d_in[1];
    const float* W_f  = (const float*)d_in[2];
    const float* U_f  = (const float*)d_in[3];
    const float* b_f  = (const float*)d_in[4];
    const float* W_b  = (const float*)d_in[5];
    const float* U_b  = (const float*)d_in[6];
    const float* b_b  = (const float*)d_in[7];
    float* out = (float*)d_out;

    cudaFuncSetAttribute(proj_kernel, cudaFuncAttributeMaxDynamicSharedMemorySize, PJ_SMEM);
    cudaFuncSetAttribute(lstm_kernel, cudaFuncAttributeMaxDynamicSharedMemorySize, RC_SMEM);

    proj_kernel<<<dim3(GDIM / 128, NROWS / 128, 2), 128, PJ_SMEM>>>(x, emb, W_f, b_f, W_b, b_b);
    lstm_kernel<<<dim3(32, 2, 2), 128, RC_SMEM>>>(x, U_f, U_b, out);
}

// round 5
// speedup vs baseline: 2.4711x; 1.3738x over previous
#include <cuda_runtime.h>
#include <cstdint>
#include <math.h>

#define NSEQ  256      // B*S
#define TLEN  128
#define EMBED 512
#define UNITS 512
#define GDIM  2048     // 4*UNITS
#define NROWS 32768    // NSEQ*TLEN
#define NBLK  128      // persistent CTAs (all co-resident, 1/SM)

// Scratch (allocation-free rule: __device__ globals)
__device__ float g_xW[2ull * NROWS * GDIM];      // [dir][n*T+t][4U]
__device__ float g_h[2][2][NSEQ][UNITS];         // [parity][dir][n][u]
__device__ unsigned g_bar_count = 0;
__device__ volatile unsigned g_bar_gen = 0;

// ---------------------------------------------------------------------------
__device__ __forceinline__ uint32_t f2tf(float f) {
    uint32_t r;
    asm("cvt.rna.tf32.f32 %0, %1;" : "=r"(r) : "f"(f));
    return r;
}

// D(16x8) += A(16x8,row) * B(8x8,col). tf32 in, f32 acc.
__device__ __forceinline__ void mma8(float* d, const uint32_t* a,
                                     uint32_t b0, uint32_t b1) {
    asm volatile(
        "mma.sync.aligned.m16n8k8.row.col.f32.tf32.tf32.f32 "
        "{%0,%1,%2,%3}, {%4,%5,%6,%7}, {%8,%9}, {%0,%1,%2,%3};"
        : "+f"(d[0]), "+f"(d[1]), "+f"(d[2]), "+f"(d[3])
        : "r"(a[0]), "r"(a[1]), "r"(a[2]), "r"(a[3]), "r"(b0), "r"(b1));
}

__device__ __forceinline__ float fsig(float x)   { return 1.0f / (1.0f + __expf(-x)); }
__device__ __forceinline__ float ftanh_(float x) { return 1.0f - 2.0f / (__expf(2.0f * x) + 1.0f); }

__device__ __forceinline__ void grid_sync() {
    __threadfence();
    __syncthreads();
    if (threadIdx.x == 0) {
        unsigned gen = g_bar_gen;
        if (atomicAdd(&g_bar_count, 1u) == NBLK - 1) {
            g_bar_count = 0;
            __threadfence();
            g_bar_gen = gen + 1;
        } else {
            while (g_bar_gen == gen) __nanosleep(32);
            __threadfence();
        }
    }
    __syncthreads();
}

// ===========================================================================
// Tensorized proj: g_xW[dir][m][:] = emb[id(dir,m)] @ W_dir + b_dir
// CTA tile M=128 x N=128, K=512 in 8 chunks of 64. 256 threads = 8 warps
// (2 row-groups x 4 col-groups); warp tile 64x32 (mt=4, nt=4).
// SMEM: A tf32 [128][68] (34816B); B tf32 [64][132] (33792B) — row-major
// padded, conflict-free float4 staging, <=2-way fragment reads;
// Z f32 stride 132 overlays A+B; ids 128.
// ===========================================================================
#define PJ_AS   0
#define PJ_BS   34816
#define PJ_IDS  68608
#define PJ_SMEM 69632

__global__ __launch_bounds__(256) void proj_kernel(
    const int*   __restrict__ x,
    const float* __restrict__ emb,
    const float* __restrict__ W_f, const float* __restrict__ b_f,
    const float* __restrict__ W_b, const float* __restrict__ b_b)
{
    extern __shared__ char smem[];
    uint32_t* As  = (uint32_t*)(smem + PJ_AS);    // stride 68
    uint32_t* Bs  = (uint32_t*)(smem + PJ_BS);    // stride 132
    float*    Zs  = (float*)smem;                 // stride 132 (overlay)
    int*      ids = (int*)(smem + PJ_IDS);

    const int tid  = threadIdx.x;
    const int lane = tid & 31;
    const int wid  = tid >> 5;
    const int wr   = wid >> 2;       // 0..1 -> 64 rows
    const int wc   = wid & 3;        // 0..3 -> 32 cols
    const int n0   = blockIdx.x * 128;
    const int row0 = blockIdx.y * 128;
    const int dir  = blockIdx.z;
    const float* __restrict__ W    = dir ? W_b : W_f;
    const float* __restrict__ bias = dir ? b_b : b_f;

    if (tid < 128) {
        int m  = row0 + tid;
        int n  = m >> 7;
        int t  = m & 127;
        int tt = dir ? (TLEN - 1 - t) : t;
        ids[tid] = x[(n << 7) + tt];
    }
    __syncthreads();

    float acc[4][4][4];
    #pragma unroll
    for (int a = 0; a < 4; a++)
        #pragma unroll
        for (int b = 0; b < 4; b++)
            #pragma unroll
            for (int c = 0; c < 4; c++) acc[a][b][c] = 0.0f;

    const int arw = tid & 127;               // A row this thread stages
    const int akh = (tid >> 7) * 32;         // k-half offset
    const float* arow = emb + (size_t)ids[arw] * EMBED + akh;

    for (int cc = 0; cc < 8; cc++) {
        // ---- stage A: 128 rows x 64 k (2 threads/row), cvt tf32 ----
        #pragma unroll
        for (int i = 0; i < 8; i++) {
            float4 v = __ldg((const float4*)(arow + cc * 64 + i * 4));
            uint4 w;
            w.x = f2tf(v.x); w.y = f2tf(v.y); w.z = f2tf(v.z); w.w = f2tf(v.w);
            *(uint4*)&As[arw * 68 + akh + i * 4] = w;
        }
        // ---- stage B: 64k x 128n row-major padded (conflict-free) ----
        #pragma unroll
        for (int it = 0; it < 8; it++) {
            int idx4 = tid + it * 256;         // 0..2047
            int kl   = idx4 >> 5;              // 0..63
            int n4   = (idx4 & 31) * 4;
            float4 v = __ldg((const float4*)(W + (size_t)(cc * 64 + kl) * GDIM + n0 + n4));
            uint4 w;
            w.x = f2tf(v.x); w.y = f2tf(v.y); w.z = f2tf(v.z); w.w = f2tf(v.w);
            *(uint4*)&Bs[kl * 132 + n4] = w;
        }
        __syncthreads();

        #pragma unroll
        for (int j = 0; j < 8; j++) {
            uint32_t afr[4][4];
            const int rb = wr * 64 + (lane >> 2);
            const int kb = j * 8 + (lane & 3);
            #pragma unroll
            for (int mt = 0; mt < 4; mt++) {
                int r = rb + mt * 16;
                afr[mt][0] = As[r * 68 + kb];
                afr[mt][1] = As[(r + 8) * 68 + kb];
                afr[mt][2] = As[r * 68 + kb + 4];
                afr[mt][3] = As[(r + 8) * 68 + kb + 4];
            }
            #pragma unroll
            for (int nt = 0; nt < 4; nt++) {
                int n = wc * 32 + nt * 8 + (lane >> 2);
                uint32_t b0 = Bs[kb * 132 + n];
                uint32_t b1 = Bs[(kb + 4) * 132 + n];
                #pragma unroll
                for (int mt = 0; mt < 4; mt++)
                    mma8(acc[mt][nt], afr[mt], b0, b1);
            }
        }
        __syncthreads();
    }

    // ---- fragments -> Z smem (overlay; k-loop done) ----
    #pragma unroll
    for (int mt = 0; mt < 4; mt++) {
        int r = wr * 64 + mt * 16 + (lane >> 2);
        #pragma unroll
        for (int nt = 0; nt < 4; nt++) {
            int c = wc * 32 + nt * 8 + 2 * (lane & 3);
            *(float2*)&Zs[r * 132 + c]       = make_float2(acc[mt][nt][0], acc[mt][nt][1]);
            *(float2*)&Zs[(r + 8) * 132 + c] = make_float2(acc[mt][nt][2], acc[mt][nt][3]);
        }
    }
    __syncthreads();

    // ---- coalesced write (+bias): 2 threads/row x 16 float4 ----
    const int orw  = tid & 127;
    const int ocol = (tid >> 7) * 64;
    float* orow = g_xW + (size_t)dir * NROWS * GDIM + (size_t)(row0 + orw) * GDIM + n0 + ocol;
    #pragma unroll
    for (int q = 0; q < 16; q++) {
        float4 v  = *(float4*)&Zs[orw * 132 + ocol + q * 4];
        float4 bv = __ldg((const float4*)(bias + n0 + ocol + q * 4));
        v.x += bv.x; v.y += bv.y; v.z += bv.z; v.w += bv.w;
        *(float4*)(orow + q * 4) = v;
    }
}

// ===========================================================================
// Persistent tf32 recurrence. Grid (32,2,2)=128 CTAs, 256 threads (8 warps).
// CTA: 128 seqs x 64 cols (16 units x 4 gates) x dir.
// B (U slice) tf32-resident [512][68] = 139264B; A double-buffer 2x[128][68]
// = 69632B; Z overlays buffer 0. One __syncthreads per K-chunk.
// Warp tile 32x32 (mt=2, nt=4). Epilogue: 2 threads/seq x 8 units, c in regs.
// ===========================================================================
#define RC_A0   0
#define RC_A1   34816
#define RC_BS   69632
#define RC_SMEM 208896

__global__ __launch_bounds__(256, 1) void lstm_kernel(
    const int*   __restrict__ x,
    const float* __restrict__ U_f,
    const float* __restrict__ U_b,
    float* __restrict__ out)
{
    extern __shared__ char smem[];
    uint32_t* Bs = (uint32_t*)(smem + RC_BS);    // stride 68
    float*    Zs = (float*)(smem + RC_A0);       // stride 68 (overlay buf0)

    const int tid  = threadIdx.x;
    const int lane = tid & 31;
    const int wid  = tid >> 5;
    const int u0   = blockIdx.x * 16;
    const int m0   = blockIdx.y * 128;
    const int dir  = blockIdx.z;
    const float* __restrict__ U = dir ? U_b : U_f;

    const int seq = tid & 127;           // CTA-local sequence row
    const int uh  = tid >> 7;            // unit-half (0/1): units uh*8..uh*8+7
    const int m   = m0 + seq;

    // ---- one-time: pack resident B (U slice) as tf32, row-major padded ----
    // B row k (0..511), col n = gate*16+u -> U col (n>>4)*512 + u0 + (n&15)
    #pragma unroll 4
    for (int it = 0; it < 128; it++) {
        int idx = tid + it * 256;         // 0..32767
        int k = idx >> 6, n = idx & 63;
        float v = U[(size_t)k * GDIM + ((n >> 4) << 9) + u0 + (n & 15)];
        Bs[k * 68 + n] = f2tf(v);
    }

    // ---- one-time: mask bits + zero h parity-0 slice ----
    unsigned mbits[4] = {0, 0, 0, 0};
    {
        const int* xr = x + (size_t)m * TLEN;
        for (int t = 0; t < TLEN; t += 4) {
            int4 v = *(const int4*)(xr + t);
            if (v.x) mbits[t >> 5]       |= 1u << (t & 31);
            if (v.y) mbits[(t + 1) >> 5] |= 1u << ((t + 1) & 31);
            if (v.z) mbits[(t + 2) >> 5] |= 1u << ((t + 2) & 31);
            if (v.w) mbits[(t + 3) >> 5] |= 1u << ((t + 3) & 31);
        }
        float4 z4 = make_float4(0.f, 0.f, 0.f, 0.f);
        float4* hp = (float4*)&g_h[0][dir][m][u0 + uh * 8];
        __stcg(hp + 0, z4); __stcg(hp + 1, z4);
    }
    __syncthreads();
    grid_sync();

    float cst[8], hst[8];
    #pragma unroll
    for (int i = 0; i < 8; i++) { cst[i] = 0.f; hst[i] = 0.f; }

    const int mb = (wid >> 1) * 32;      // warp row base
    const int nb = (wid & 1) * 32;       // warp col base
    const int akh = uh * 32;             // A staging k-half offset

    for (int t = 0; t < TLEN; t++) {
        const int par = t & 1;
        const float* __restrict__ hrow = &g_h[par][dir][m0 + seq][akh];

        float acc[2][4][4];
        #pragma unroll
        for (int a = 0; a < 2; a++)
            #pragma unroll
            for (int b = 0; b < 4; b++)
                #pragma unroll
                for (int c = 0; c < 4; c++) acc[a][b][c] = 0.0f;

        // prefetch chunk 0 of h (32 floats/thread)
        float4 pf[8];
        #pragma unroll
        for (int i = 0; i < 8; i++)
            pf[i] = __ldcg((const float4*)(hrow) + i);

        float zx[32];

        #pragma unroll 1
        for (int cc = 0; cc < 8; cc++) {
            uint32_t* Ab = (uint32_t*)(smem + ((cc & 1) ? RC_A1 : RC_A0));
            // stage prefetched chunk -> A buf (cvt tf32); conflict-free
            #pragma unroll
            for (int i = 0; i < 8; i++) {
                uint4 w;
                w.x = f2tf(pf[i].x); w.y = f2tf(pf[i].y);
                w.z = f2tf(pf[i].z); w.w = f2tf(pf[i].w);
                *(uint4*)&Ab[seq * 68 + akh + i * 4] = w;
            }
            __syncthreads();

            if (cc < 7) {                 // prefetch next chunk (overlaps mma)
                #pragma unroll
                for (int i = 0; i < 8; i++)
                    pf[i] = __ldcg((const float4*)(hrow + (cc + 1) * 64) + i);
            } else {                      // prefetch xW gate pre-activations
                const float* xw = g_xW + ((size_t)dir * NROWS + (size_t)m * TLEN + t) * GDIM
                                + u0 + uh * 8;
                #pragma unroll
                for (int g = 0; g < 4; g++) {
                    float4 v0 = __ldcs((const float4*)(xw + g * 512));
                    float4 v1 = __ldcs((const float4*)(xw + g * 512 + 4));
                    zx[g * 8 + 0] = v0.x; zx[g * 8 + 1] = v0.y;
                    zx[g * 8 + 2] = v0.z; zx[g * 8 + 3] = v0.w;
                    zx[g * 8 + 4] = v1.x; zx[g * 8 + 5] = v1.y;
                    zx[g * 8 + 6] = v1.z; zx[g * 8 + 7] = v1.w;
                }
            }

            #pragma unroll
            for (int j = 0; j < 8; j++) {
                const int kb = j * 8 + (lane & 3);        // chunk-local k
                uint32_t afr[2][4];
                #pragma unroll
                for (int mt = 0; mt < 2; mt++) {
                    int r = mb + mt * 16 + (lane >> 2);
                    afr[mt][0] = Ab[r * 68 + kb];
                    afr[mt][1] = Ab[(r + 8) * 68 + kb];
                    afr[mt][2] = Ab[r * 68 + kb + 4];
                    afr[mt][3] = Ab[(r + 8) * 68 + kb + 4];
                }
                const int kg = cc * 64 + kb;              // global k
                #pragma unroll
                for (int nt = 0; nt < 4; nt++) {
                    int n = nb + nt * 8 + (lane >> 2);
                    uint32_t b0 = Bs[kg * 68 + n];
                    uint32_t b1 = Bs[(kg + 4) * 68 + n];
                    mma8(acc[0][nt], afr[0], b0, b1);
                    mma8(acc[1][nt], afr[1], b0, b1);
                }
            }
        }
        __syncthreads();   // all mma (incl. buf0 cc=6) done before Z overlay

        // ---- fragments -> Z smem (stride 68, overlays buf0) ----
        #pragma unroll
        for (int mt = 0; mt < 2; mt++) {
            int r = mb + mt * 16 + (lane >> 2);
            #pragma unroll
            for (int nt = 0; nt < 4; nt++) {
                int c = nb + nt * 8 + 2 * (lane & 3);
                *(float2*)&Zs[r * 68 + c]       = make_float2(acc[mt][nt][0], acc[mt][nt][1]);
                *(float2*)&Zs[(r + 8) * 68 + c] = make_float2(acc[mt][nt][2], acc[mt][nt][3]);
            }
        }
        __syncthreads();

        // ---- gate math + masked update (2 threads/seq, 8 units each) ----
        const int  tt = dir ? (TLEN - 1 - t) : t;
        const bool mv = (mbits[tt >> 5] >> (tt & 31)) & 1;

        float zg4[4][8];
        #pragma unroll
        for (int g = 0; g < 4; g++) {
            float4 v0 = *(float4*)&Zs[seq * 68 + g * 16 + uh * 8];
            float4 v1 = *(float4*)&Zs[seq * 68 + g * 16 + uh * 8 + 4];
            zg4[g][0] = v0.x; zg4[g][1] = v0.y; zg4[g][2] = v0.z; zg4[g][3] = v0.w;
            zg4[g][4] = v1.x; zg4[g][5] = v1.y; zg4[g][6] = v1.z; zg4[g][7] = v1.w;
        }

        #pragma unroll
        for (int u = 0; u < 8; u++) {
            float zi = zx[u]      + zg4[0][u];
            float zf = zx[8 + u]  + zg4[1][u];
            float zg = zx[16 + u] + zg4[2][u];
            float zo = zx[24 + u] + zg4[3][u];
            float ig = fsig(zi);
            float fg = fsig(zf);
            float gg = ftanh_(zg);
            float og = fsig(zo);
            float cn = fg * cst[u] + ig * gg;
            float hn = og * ftanh_(cn);
            if (mv) { cst[u] = cn; hst[u] = hn; }
        }

        // ---- store h(t+1) ----
        {
            float4* hdst = (float4*)&g_h[par ^ 1][dir][m][u0 + uh * 8];
            __stcg(hdst + 0, make_float4(hst[0], hst[1], hst[2], hst[3]));
            __stcg(hdst + 1, make_float4(hst[4], hst[5], hst[6], hst[7]));
        }
        grid_sync();
    }

    // ---- final output ----
    {
        float* op = out + (size_t)m * 1024 + dir * 512 + u0 + uh * 8;
        *(float4*)(op + 0) = make_float4(hst[0], hst[1], hst[2], hst[3]);
        *(float4*)(op + 4) = make_float4(hst[4], hst[5], hst[6], hst[7]);
    }
}

// ===========================================================================
extern "C" void kernel_launch(void* const* d_in, const int* in_sizes, int n_in,
                              void* d_out, int out_size)
{
    const int*   x    = (const int*)  d_in[0];
    const float* emb  = (const float*)d_in[1];
    const float* W_f  = (const float*)d_in[2];
    const float* U_f  = (const float*)d_in[3];
    const float* b_f  = (const float*)d_in[4];
    const float* W_b  = (const float*)d_in[5];
    const float* U_b  = (const float*)d_in[6];
    const float* b_b  = (const float*)d_in[7];
    float* out = (float*)d_out;

    cudaFuncSetAttribute(proj_kernel, cudaFuncAttributeMaxDynamicSharedMemorySize, PJ_SMEM);
    cudaFuncSetAttribute(lstm_kernel, cudaFuncAttributeMaxDynamicSharedMemorySize, RC_SMEM);

    proj_kernel<<<dim3(GDIM / 128, NROWS / 128, 2), 256, PJ_SMEM>>>(x, emb, W_f, b_f, W_b, b_b);
    lstm_kernel<<<dim3(32, 2, 2), 256, RC_SMEM>>>(x, U_f, U_b, out);
}

// round 9
// speedup vs baseline: 2.5516x; 1.0326x over previous
#include <cuda_runtime.h>
#include <cuda_fp16.h>
#include <cstdint>
#include <math.h>

#define NSEQ  256      // B*S
#define TLEN  128
#define EMBED 512
#define UNITS 512
#define GDIM  2048     // 4*UNITS
#define NROWS 32768    // NSEQ*TLEN
#define NGRP  32       // CTAs per barrier group (one m-block x dir)

// Scratch (allocation-free rule: __device__ globals)
__device__ float g_xW[2ull * NROWS * GDIM];      // [dir][n*T+t][4U]
__device__ float g_h[2][2][NSEQ][UNITS];         // [parity][dir][n][u]
__device__ unsigned g_bcnt[4 * 32];              // per-group counters, 128B apart
__device__ volatile unsigned g_bgen[4 * 32];

// ---------------------------------------------------------------------------
// fp16 mma helpers (legacy mma.sync path; tcgen05 unavailable on this target)
// ---------------------------------------------------------------------------
// D(16x8) += A(16x16,row) * B(16x8,col). fp16 in, f32 acc.
__device__ __forceinline__ void mma16(float* d, uint32_t a0, uint32_t a1,
                                      uint32_t a2, uint32_t a3,
                                      uint32_t b0, uint32_t b1) {
    asm volatile(
        "mma.sync.aligned.m16n8k16.row.col.f32.f16.f16.f32 "
        "{%0,%1,%2,%3}, {%4,%5,%6,%7}, {%8,%9}, {%0,%1,%2,%3};"
        : "+f"(d[0]), "+f"(d[1]), "+f"(d[2]), "+f"(d[3])
        : "r"(a0), "r"(a1), "r"(a2), "r"(a3), "r"(b0), "r"(b1));
}

// column permutation inside a 16-k block so (2q,2q+1,2q+8,2q+9) land at 4q..4q+3
__device__ __forceinline__ int koff16(int kk) {
    return ((kk >> 1) & 3) * 4 + ((kk >> 3) & 1) * 2 + (kk & 1);
}

__device__ __forceinline__ float fsig(float x)   { return 1.0f / (1.0f + __expf(-x)); }
__device__ __forceinline__ float ftanh_(float x) { return 1.0f - 2.0f / (__expf(2.0f * x) + 1.0f); }

__device__ __forceinline__ void group_sync(int gi) {
    __threadfence();
    __syncthreads();
    if (threadIdx.x == 0) {
        unsigned gen = g_bgen[gi * 32];
        if (atomicAdd(&g_bcnt[gi * 32], 1u) == NGRP - 1) {
            g_bcnt[gi * 32] = 0;
            __threadfence();
            g_bgen[gi * 32] = gen + 1;
        } else {
            while (g_bgen[gi * 32] == gen) __nanosleep(32);
            __threadfence();
        }
    }
    __syncthreads();
}

// ===========================================================================
// Tensorized proj (fp16 mma): g_xW[dir][m][:] = emb[id(dir,m)] @ W_dir + b
// CTA tile M=128 x N=128, K=512 in 8 chunks of 64. 256 threads = 8 warps
// (2 row-groups x 4 col-groups); warp tile 64x32 (mt=4, nt=4).
// SMEM: A half [128][68] @0; B half [128][68] @17408 ([n][k_perm]);
// Z f32 [128][132] @0 overlays A+B (written only after final k-loop sync).
// ===========================================================================
#define PJ_AS   0
#define PJ_BS   17408
#define PJ_IDS  67584
#define PJ_SMEM 68096

__global__ __launch_bounds__(256) void proj_kernel(
    const int*   __restrict__ x,
    const float* __restrict__ emb,
    const float* __restrict__ W_f, const float* __restrict__ b_f,
    const float* __restrict__ W_b, const float* __restrict__ b_b)
{
    extern __shared__ char smem[];
    __half* As = (__half*)(smem + PJ_AS);    // stride 68 halves
    __half* Bs = (__half*)(smem + PJ_BS);    // stride 68 halves, [n][k_perm]
    float*  Zs = (float*)smem;               // stride 132 words (overlay)
    int*   ids = (int*)(smem + PJ_IDS);

    const int tid  = threadIdx.x;
    const int lane = tid & 31;
    const int wid  = tid >> 5;
    const int wr   = wid >> 2;       // 0..1 -> 64 rows
    const int wc   = wid & 3;        // 0..3 -> 32 cols
    const int n0   = blockIdx.x * 128;
    const int row0 = blockIdx.y * 128;
    const int dir  = blockIdx.z;
    const float* __restrict__ W    = dir ? W_b : W_f;
    const float* __restrict__ bias = dir ? b_b : b_f;

    if (tid < 128) {
        int m  = row0 + tid;
        int n  = m >> 7;
        int t  = m & 127;
        int tt = dir ? (TLEN - 1 - t) : t;
        ids[tid] = x[(n << 7) + tt];
    }
    __syncthreads();

    float acc[4][4][4];
    #pragma unroll
    for (int a = 0; a < 4; a++)
        #pragma unroll
        for (int b = 0; b < 4; b++)
            #pragma unroll
            for (int c = 0; c < 4; c++) acc[a][b][c] = 0.0f;

    const int arw = tid & 127;               // A row this thread stages
    const int akh = (tid >> 7) * 32;         // k-half offset (0 or 32)
    const float* arow = emb + (size_t)ids[arw] * EMBED + akh;

    for (int cc = 0; cc < 8; cc++) {
        // ---- stage A: 128 rows x 64 k (2 threads/row), pair-permuted fp16 ----
        #pragma unroll
        for (int i = 0; i < 8; i++) {
            float4 v = __ldg((const float4*)(arow + cc * 64 + i * 4));
            int kl   = akh + i * 4;                        // chunk-local k
            int base = arw * 68 + (kl >> 4) * 16 + koff16(kl & 15);
            __half2* dst = (__half2*)&As[base];
            dst[0] = __floats2half2_rn(v.x, v.y);
            dst[2] = __floats2half2_rn(v.z, v.w);
        }
        // ---- stage B: 64k x 128n -> [n][k_perm] fp16 ----
        #pragma unroll
        for (int it = 0; it < 8; it++) {
            int idx4 = tid + it * 256;         // 0..2047
            int kl   = idx4 >> 5;              // 0..63 (uniform per warp)
            int n4   = (idx4 & 31) * 4;
            float4 v = __ldg((const float4*)(W + (size_t)(cc * 64 + kl) * GDIM + n0 + n4));
            int pos = (kl >> 4) * 16 + koff16(kl & 15);
            Bs[(n4 + 0) * 68 + pos] = __float2half_rn(v.x);
            Bs[(n4 + 1) * 68 + pos] = __float2half_rn(v.y);
            Bs[(n4 + 2) * 68 + pos] = __float2half_rn(v.z);
            Bs[(n4 + 3) * 68 + pos] = __float2half_rn(v.w);
        }
        __syncthreads();

        #pragma unroll
        for (int j = 0; j < 4; j++) {
            const int q4 = (lane & 3) * 4;
            uint2 av[4][2];
            #pragma unroll
            for (int mt = 0; mt < 4; mt++) {
                int r = wr * 64 + mt * 16 + (lane >> 2);
                av[mt][0] = *(const uint2*)&As[r * 68 + j * 16 + q4];
                av[mt][1] = *(const uint2*)&As[(r + 8) * 68 + j * 16 + q4];
            }
            #pragma unroll
            for (int nt = 0; nt < 4; nt++) {
                int n = wc * 32 + nt * 8 + (lane >> 2);
                uint2 bb = *(const uint2*)&Bs[n * 68 + j * 16 + q4];
                #pragma unroll
                for (int mt = 0; mt < 4; mt++)
                    mma16(acc[mt][nt], av[mt][0].x, av[mt][1].x,
                          av[mt][0].y, av[mt][1].y, bb.x, bb.y);
            }
        }
        __syncthreads();
    }

    // ---- fragments -> Z smem (stride 132; overlay valid after final sync) ----
    #pragma unroll
    for (int mt = 0; mt < 4; mt++) {
        int r = wr * 64 + mt * 16 + (lane >> 2);
        #pragma unroll
        for (int nt = 0; nt < 4; nt++) {
            int c = wc * 32 + nt * 8 + 2 * (lane & 3);
            *(float2*)&Zs[r * 132 + c]       = make_float2(acc[mt][nt][0], acc[mt][nt][1]);
            *(float2*)&Zs[(r + 8) * 132 + c] = make_float2(acc[mt][nt][2], acc[mt][nt][3]);
        }
    }
    __syncthreads();

    // ---- coalesced write (+bias): 2 threads/row x 16 float4 ----
    const int orw  = tid & 127;
    const int ocol = (tid >> 7) * 64;
    float* orow = g_xW + (size_t)dir * NROWS * GDIM + (size_t)(row0 + orw) * GDIM + n0 + ocol;
    #pragma unroll
    for (int q = 0; q < 16; q++) {
        float4 v  = *(float4*)&Zs[orw * 132 + ocol + q * 4];
        float4 bv = __ldg((const float4*)(bias + n0 + ocol + q * 4));
        v.x += bv.x; v.y += bv.y; v.z += bv.z; v.w += bv.w;
        *(float4*)(orow + q * 4) = v;
    }
}

// ===========================================================================
// Persistent fp16 recurrence. Grid (32,2,2)=128 CTAs, 256 threads (8 warps).
// CTA: 128 seqs x 64 cols (16 units x 4 gates) x dir.
// B (U slice) fp16-resident [64 n][512 k perm, stride 520] = 66560B;
// A double-buffer 2x[128][68]h = 34816B; Z f32 [128][68]w overlays both A
// buffers exactly (34816B). Warp tile 32x32 (mt=2, nt=4).
// ===========================================================================
#define RC_A0   0
#define RC_A1   17408
#define RC_BS   34816
#define RC_SMEM 101376

__global__ __launch_bounds__(256, 1) void lstm_kernel(
    const int*   __restrict__ x,
    const float* __restrict__ U_f,
    const float* __restrict__ U_b,
    float* __restrict__ out)
{
    extern __shared__ char smem[];
    __half* Bs = (__half*)(smem + RC_BS);    // [n][k_perm], stride 520 halves
    float*  Zs = (float*)(smem + RC_A0);     // stride 68 words (overlays A0+A1)

    const int tid  = threadIdx.x;
    const int lane = tid & 31;
    const int wid  = tid >> 5;
    const int u0   = blockIdx.x * 16;
    const int m0   = blockIdx.y * 128;
    const int dir  = blockIdx.z;
    const int gi   = blockIdx.y * 2 + blockIdx.z;   // barrier group
    const float* __restrict__ U = dir ? U_b : U_f;

    const int seq = tid & 127;           // CTA-local sequence row
    const int uh  = tid >> 7;            // unit-half (0/1): units uh*8..uh*8+7
    const int m   = m0 + seq;

    // ---- one-time: pack resident B (U slice) as fp16, [n][k_perm] ----
    // col(n) = (n>>4)*512 + u0 + (n&15)
    #pragma unroll 4
    for (int it = 0; it < 128; it++) {
        int idx = tid + it * 256;         // 0..32767
        int k = idx >> 6, n = idx & 63;
        float v = U[(size_t)k * GDIM + ((n >> 4) << 9) + u0 + (n & 15)];
        Bs[n * 520 + (k >> 4) * 16 + koff16(k & 15)] = __float2half_rn(v);
    }

    // ---- one-time: mask bits + zero h parity-0 slice ----
    unsigned mbits[4] = {0, 0, 0, 0};
    {
        const int* xr = x + (size_t)m * TLEN;
        for (int t = 0; t < TLEN; t += 4) {
            int4 v = *(const int4*)(xr + t);
            if (v.x) mbits[t >> 5]       |= 1u << (t & 31);
            if (v.y) mbits[(t + 1) >> 5] |= 1u << ((t + 1) & 31);
            if (v.z) mbits[(t + 2) >> 5] |= 1u << ((t + 2) & 31);
            if (v.w) mbits[(t + 3) >> 5] |= 1u << ((t + 3) & 31);
        }
        float4 z4 = make_float4(0.f, 0.f, 0.f, 0.f);
        float4* hp = (float4*)&g_h[0][dir][m][u0 + uh * 8];
        __stcg(hp + 0, z4); __stcg(hp + 1, z4);
    }
    __syncthreads();
    group_sync(gi);

    float cst[8], hst[8];
    #pragma unroll
    for (int i = 0; i < 8; i++) { cst[i] = 0.f; hst[i] = 0.f; }

    const int mb  = (wid >> 1) * 32;     // warp row base
    const int nb  = (wid & 1) * 32;      // warp col base
    const int akh = uh * 32;             // A staging k-half offset

    for (int t = 0; t < TLEN; t++) {
        const int par = t & 1;
        const float* __restrict__ hrow = &g_h[par][dir][m0 + seq][akh];

        float acc[2][4][4];
        #pragma unroll
        for (int a = 0; a < 2; a++)
            #pragma unroll
            for (int b = 0; b < 4; b++)
                #pragma unroll
                for (int c = 0; c < 4; c++) acc[a][b][c] = 0.0f;

        // prefetch chunk 0 of h (32 floats/thread)
        float4 pf[8];
        #pragma unroll
        for (int i = 0; i < 8; i++)
            pf[i] = __ldcg((const float4*)(hrow) + i);

        float zx[32];

        #pragma unroll 1
        for (int cc = 0; cc < 8; cc++) {
            __half* Ab = (__half*)(smem + ((cc & 1) ? RC_A1 : RC_A0));
            // stage prefetched chunk -> A buf (pair-permuted fp16)
            #pragma unroll
            for (int i = 0; i < 8; i++) {
                int kl   = akh + i * 4;
                int base = seq * 68 + (kl >> 4) * 16 + koff16(kl & 15);
                __half2* dst = (__half2*)&Ab[base];
                dst[0] = __floats2half2_rn(pf[i].x, pf[i].y);
                dst[2] = __floats2half2_rn(pf[i].z, pf[i].w);
            }
            __syncthreads();

            if (cc < 7) {                 // prefetch next chunk (overlaps mma)
                #pragma unroll
                for (int i = 0; i < 8; i++)
                    pf[i] = __ldcg((const float4*)(hrow + (cc + 1) * 64) + i);
            } else {                      // prefetch xW gate pre-activations
                const float* xw = g_xW + ((size_t)dir * NROWS + (size_t)m * TLEN + t) * GDIM
                                + u0 + uh * 8;
                #pragma unroll
                for (int g = 0; g < 4; g++) {
                    float4 v0 = __ldcs((const float4*)(xw + g * 512));
                    float4 v1 = __ldcs((const float4*)(xw + g * 512 + 4));
                    zx[g * 8 + 0] = v0.x; zx[g * 8 + 1] = v0.y;
                    zx[g * 8 + 2] = v0.z; zx[g * 8 + 3] = v0.w;
                    zx[g * 8 + 4] = v1.x; zx[g * 8 + 5] = v1.y;
                    zx[g * 8 + 6] = v1.z; zx[g * 8 + 7] = v1.w;
                }
            }

            #pragma unroll
            for (int j = 0; j < 4; j++) {
                const int q4 = (lane & 3) * 4;
                uint2 av[2][2];
                #pragma unroll
                for (int mt = 0; mt < 2; mt++) {
                    int r = mb + mt * 16 + (lane >> 2);
                    av[mt][0] = *(const uint2*)&Ab[r * 68 + j * 16 + q4];
                    av[mt][1] = *(const uint2*)&Ab[(r + 8) * 68 + j * 16 + q4];
                }
                const int kg = cc * 4 + j;            // global 16-k block
                #pragma unroll
                for (int nt = 0; nt < 4; nt++) {
                    int n = nb + nt * 8 + (lane >> 2);
                    uint2 bb = *(const uint2*)&Bs[n * 520 + kg * 16 + q4];
                    mma16(acc[0][nt], av[0][0].x, av[0][1].x, av[0][0].y, av[0][1].y,
                          bb.x, bb.y);
                    mma16(acc[1][nt], av[1][0].x, av[1][1].x, av[1][0].y, av[1][1].y,
                          bb.x, bb.y);
                }
            }
        }
        __syncthreads();   // all mma done before Z overlays A buffers

        // ---- fragments -> Z smem (stride 68 words, overlays A0+A1) ----
        #pragma unroll
        for (int mt = 0; mt < 2; mt++) {
            int r = mb + mt * 16 + (lane >> 2);
            #pragma unroll
            for (int nt = 0; nt < 4; nt++) {
                int c = nb + nt * 8 + 2 * (lane & 3);
                *(float2*)&Zs[r * 68 + c]       = make_float2(acc[mt][nt][0], acc[mt][nt][1]);
                *(float2*)&Zs[(r + 8) * 68 + c] = make_float2(acc[mt][nt][2], acc[mt][nt][3]);
            }
        }
        __syncthreads();

        // ---- gate math + masked update (2 threads/seq, 8 units each) ----
        const int  tt = dir ? (TLEN - 1 - t) : t;
        const bool mv = (mbits[tt >> 5] >> (tt & 31)) & 1;

        float zg4[4][8];
        #pragma unroll
        for (int g = 0; g < 4; g++) {
            float4 v0 = *(float4*)&Zs[seq * 68 + g * 16 + uh * 8];
            float4 v1 = *(float4*)&Zs[seq * 68 + g * 16 + uh * 8 + 4];
            zg4[g][0] = v0.x; zg4[g][1] = v0.y; zg4[g][2] = v0.z; zg4[g][3] = v0.w;
            zg4[g][4] = v1.x; zg4[g][5] = v1.y; zg4[g][6] = v1.z; zg4[g][7] = v1.w;
        }

        #pragma unroll
        for (int u = 0; u < 8; u++) {
            float zi = zx[u]      + zg4[0][u];
            float zf = zx[8 + u]  + zg4[1][u];
            float zg = zx[16 + u] + zg4[2][u];
            float zo = zx[24 + u] + zg4[3][u];
            float ig = fsig(zi);
            float fg = fsig(zf);
            float gg = ftanh_(zg);
            float og = fsig(zo);
            float cn = fg * cst[u] + ig * gg;
            float hn = og * ftanh_(cn);
            if (mv) { cst[u] = cn; hst[u] = hn; }
        }

        // ---- store h(t+1) ----
        {
            float4* hdst = (float4*)&g_h[par ^ 1][dir][m][u0 + uh * 8];
            __stcg(hdst + 0, make_float4(hst[0], hst[1], hst[2], hst[3]));
            __stcg(hdst + 1, make_float4(hst[4], hst[5], hst[6], hst[7]));
        }
        group_sync(gi);
    }

    // ---- final output ----
    {
        float* op = out + (size_t)m * 1024 + dir * 512 + u0 + uh * 8;
        *(float4*)(op + 0) = make_float4(hst[0], hst[1], hst[2], hst[3]);
        *(float4*)(op + 4) = make_float4(hst[4], hst[5], hst[6], hst[7]);
    }
}

// ===========================================================================
extern "C" void kernel_launch(void* const* d_in, const int* in_sizes, int n_in,
                              void* d_out, int out_size)
{
    const int*   x    = (const int*)  d_in[0];
    const float* emb  = (const float*)d_in[1];
    const float* W_f  = (const float*)d_in[2];
    const float* U_f  = (const float*)d_in[3];
    const float* b_f  = (const float*)d_in[4];
    const float* W_b  = (const float*)d_in[5];
    const float* U_b  = (const float*)d_in[6];
    const float* b_b  = (const float*)d_in[7];
    float* out = (float*)d_out;

    cudaFuncSetAttribute(proj_kernel, cudaFuncAttributeMaxDynamicSharedMemorySize, PJ_SMEM);
    cudaFuncSetAttribute(lstm_kernel, cudaFuncAttributeMaxDynamicSharedMemorySize, RC_SMEM);

    proj_kernel<<<dim3(GDIM / 128, NROWS / 128, 2), 256, PJ_SMEM>>>(x, emb, W_f, b_f, W_b, b_b);
    lstm_kernel<<<dim3(32, 2, 2), 256, RC_SMEM>>>(x, U_f, U_b, out);
}

// round 10
// speedup vs baseline: 3.5889x; 1.4065x over previous
#include <cuda_runtime.h>
#include <cuda_fp16.h>
#include <cstdint>
#include <math.h>

#define NSEQ  256      // B*S
#define TLEN  128
#define EMBED 512
#define UNITS 512
#define GDIM  2048     // 4*UNITS
#define NROWS 32768    // NSEQ*TLEN
#define NGRP  32       // CTAs per barrier group (one m-block x dir)

// Scratch (allocation-free rule: __device__ globals)
// g_xW layout: [dir][u_slice(32)][t(128)][seq(256)][64]  (slice = 16 units x 4 gates,
// col c = gate*16 + u). Per (dir,slice,t): 256*64 floats contiguous.
__device__ float g_xW[2ull * NROWS * GDIM];
__device__ float g_h[2][2][NSEQ][UNITS];         // [parity][dir][n][u]
__device__ unsigned g_bcnt[4 * 32];              // per-group counters
__device__ volatile unsigned g_bgen[4 * 32];

#define XW2_BASE(dir, sl, t) ((((size_t)(dir) * 32 + (sl)) * 128 + (t)) * (256 * 64))

// ---------------------------------------------------------------------------
// fp16 mma helpers (legacy mma.sync path; tcgen05 unavailable on this target)
// ---------------------------------------------------------------------------
__device__ __forceinline__ void mma16(float* d, uint32_t a0, uint32_t a1,
                                      uint32_t a2, uint32_t a3,
                                      uint32_t b0, uint32_t b1) {
    asm volatile(
        "mma.sync.aligned.m16n8k16.row.col.f32.f16.f16.f32 "
        "{%0,%1,%2,%3}, {%4,%5,%6,%7}, {%8,%9}, {%0,%1,%2,%3};"
        : "+f"(d[0]), "+f"(d[1]), "+f"(d[2]), "+f"(d[3])
        : "r"(a0), "r"(a1), "r"(a2), "r"(a3), "r"(b0), "r"(b1));
}

// column permutation inside a 16-k block so (2q,2q+1,2q+8,2q+9) land at 4q..4q+3
__device__ __forceinline__ int koff16(int kk) {
    return ((kk >> 1) & 3) * 4 + ((kk >> 3) & 1) * 2 + (kk & 1);
}

__device__ __forceinline__ float fsig(float x)   { return 1.0f / (1.0f + __expf(-x)); }
__device__ __forceinline__ float ftanh_(float x) { return 1.0f - 2.0f / (__expf(2.0f * x) + 1.0f); }

__device__ __forceinline__ void group_sync(int gi) {
    __threadfence();
    __syncthreads();
    if (threadIdx.x == 0) {
        unsigned gen = g_bgen[gi * 32];
        if (atomicAdd(&g_bcnt[gi * 32], 1u) == NGRP - 1) {
            g_bcnt[gi * 32] = 0;
            __threadfence();
            g_bgen[gi * 32] = gen + 1;
        } else {
            while (g_bgen[gi * 32] == gen) __nanosleep(32);
            __threadfence();
        }
    }
    __syncthreads();
}

// ===========================================================================
// Tensorized proj (fp16 mma). CTA = (seq n = blockIdx.y, 128 t-rows) x
// (128 cols of gate g = n0/512) x dir. K=512 in 8 chunks of 64.
// 256 threads = 8 warps (2 row-groups x 4 col-groups); warp tile 64x32.
// A staging COALESCED: 16 lanes cover one emb row's 256B chunk slice.
// Output goes to transposed g_xW layout (8 slices x 16 cols each).
// ===========================================================================
#define PJ_AS   0
#define PJ_BS   17408
#define PJ_IDS  67584
#define PJ_SMEM 68096

__global__ __launch_bounds__(256) void proj_kernel(
    const int*   __restrict__ x,
    const float* __restrict__ emb,
    const float* __restrict__ W_f, const float* __restrict__ b_f,
    const float* __restrict__ W_b, const float* __restrict__ b_b)
{
    extern __shared__ char smem[];
    __half* As = (__half*)(smem + PJ_AS);    // stride 68 halves, k-pair-permuted
    __half* Bs = (__half*)(smem + PJ_BS);    // stride 68 halves, [n][k_perm]
    float*  Zs = (float*)smem;               // stride 132 words (overlay)
    int*   ids = (int*)(smem + PJ_IDS);

    const int tid  = threadIdx.x;
    const int lane = tid & 31;
    const int wid  = tid >> 5;
    const int wr   = wid >> 2;       // 0..1 -> 64 rows
    const int wc   = wid & 3;        // 0..3 -> 32 cols
    const int n0   = blockIdx.x * 128;
    const int nseq = blockIdx.y;     // this CTA's sequence
    const int dir  = blockIdx.z;
    const float* __restrict__ W    = dir ? W_b : W_f;
    const float* __restrict__ bias = dir ? b_b : b_f;

    if (tid < 128) {
        int t  = tid;
        int tt = dir ? (TLEN - 1 - t) : t;
        ids[tid] = x[(nseq << 7) + tt];
    }
    __syncthreads();

    float acc[4][4][4];
    #pragma unroll
    for (int a = 0; a < 4; a++)
        #pragma unroll
        for (int b = 0; b < 4; b++)
            #pragma unroll
            for (int c = 0; c < 4; c++) acc[a][b][c] = 0.0f;

    const int aq  = tid & 15;        // float4 index within 64-float chunk
    const int ar0 = tid >> 4;        // base row (t)

    for (int cc = 0; cc < 8; cc++) {
        // ---- stage A coalesced: warp = 2 rows x 256B; pair-permuted fp16 ----
        {
            int kl   = aq * 4;
            int pbase = (kl >> 4) * 16 + koff16(kl & 15);
            #pragma unroll
            for (int i = 0; i < 8; i++) {
                int row = ar0 + i * 16;
                float4 v = __ldg((const float4*)(emb + (size_t)ids[row] * EMBED
                                                 + cc * 64 + kl));
                __half2* dst = (__half2*)&As[row * 68 + pbase];
                dst[0] = __floats2half2_rn(v.x, v.y);
                dst[2] = __floats2half2_rn(v.z, v.w);
            }
        }
        // ---- stage B: 64k x 128n -> [n][k_perm] fp16 (coalesced) ----
        #pragma unroll
        for (int it = 0; it < 8; it++) {
            int idx4 = tid + it * 256;         // 0..2047
            int kl   = idx4 >> 5;              // 0..63
            int n4   = (idx4 & 31) * 4;
            float4 v = __ldg((const float4*)(W + (size_t)(cc * 64 + kl) * GDIM + n0 + n4));
            int pos = (kl >> 4) * 16 + koff16(kl & 15);
            Bs[(n4 + 0) * 68 + pos] = __float2half_rn(v.x);
            Bs[(n4 + 1) * 68 + pos] = __float2half_rn(v.y);
            Bs[(n4 + 2) * 68 + pos] = __float2half_rn(v.z);
            Bs[(n4 + 3) * 68 + pos] = __float2half_rn(v.w);
        }
        __syncthreads();

        #pragma unroll
        for (int j = 0; j < 4; j++) {
            const int q4 = (lane & 3) * 4;
            uint2 av[4][2];
            #pragma unroll
            for (int mt = 0; mt < 4; mt++) {
                int r = wr * 64 + mt * 16 + (lane >> 2);
                av[mt][0] = *(const uint2*)&As[r * 68 + j * 16 + q4];
                av[mt][1] = *(const uint2*)&As[(r + 8) * 68 + j * 16 + q4];
            }
            #pragma unroll
            for (int nt = 0; nt < 4; nt++) {
                int n = wc * 32 + nt * 8 + (lane >> 2);
                uint2 bb = *(const uint2*)&Bs[n * 68 + j * 16 + q4];
                #pragma unroll
                for (int mt = 0; mt < 4; mt++)
                    mma16(acc[mt][nt], av[mt][0].x, av[mt][1].x,
                          av[mt][0].y, av[mt][1].y, bb.x, bb.y);
            }
        }
        __syncthreads();
    }

    // ---- fragments -> Z smem (stride 132; overlay valid after final sync) ----
    #pragma unroll
    for (int mt = 0; mt < 4; mt++) {
        int r = wr * 64 + mt * 16 + (lane >> 2);
        #pragma unroll
        for (int nt = 0; nt < 4; nt++) {
            int c = wc * 32 + nt * 8 + 2 * (lane & 3);
            *(float2*)&Zs[r * 132 + c]       = make_float2(acc[mt][nt][0], acc[mt][nt][1]);
            *(float2*)&Zs[(r + 8) * 132 + c] = make_float2(acc[mt][nt][2], acc[mt][nt][3]);
        }
    }
    __syncthreads();

    // ---- write to transposed g_xW (+bias) ----
    // col j = n0 + cz; gate g = n0>>9; slice = us0 + cz/16; in-slice col = g*16 + cz%16
    {
        const int g   = n0 >> 9;
        const int us0 = (n0 & 511) >> 4;
        #pragma unroll
        for (int it = 0; it < 16; it++) {
            int e  = tid + it * 256;          // 0..4095 float4s
            int c4 = e & 3;
            int t  = (e >> 2) & 127;
            int si = e >> 9;
            int cz = si * 16 + c4 * 4;
            float4 v  = *(float4*)&Zs[t * 132 + cz];
            float4 bv = __ldg((const float4*)(bias + n0 + cz));
            v.x += bv.x; v.y += bv.y; v.z += bv.z; v.w += bv.w;
            size_t idx = XW2_BASE(dir, us0 + si, t) + (size_t)nseq * 64 + g * 16 + c4 * 4;
            *(float4*)(g_xW + idx) = v;
        }
    }
}

// ===========================================================================
// Persistent fp16 recurrence. Grid (32,2,2)=128 CTAs, 256 threads (8 warps).
// CTA: 128 seqs x 64 cols (slice = 16 units x 4 gates) x dir.
// COALESCED h staging (warp = 2 rows x 256B); xW read is one contiguous
// 32KB block per step, exchanged via xWbuf smem.
// SMEM: A 2x[128][68]h (34816) @0 (Z f32 overlays); B [64][520]h (66560)
// @34816; xWbuf [128][68]f (34816) @101376. Total 136192.
// ===========================================================================
#define RC_A0   0
#define RC_A1   17408
#define RC_BS   34816
#define RC_XW   101376
#define RC_SMEM 136192

__global__ __launch_bounds__(256, 1) void lstm_kernel(
    const int*   __restrict__ x,
    const float* __restrict__ U_f,
    const float* __restrict__ U_b,
    float* __restrict__ out)
{
    extern __shared__ char smem[];
    __half* Bs  = (__half*)(smem + RC_BS);   // [n][k_perm], stride 520 halves
    float*  Zs  = (float*)(smem + RC_A0);    // stride 68 words (overlays A0+A1)
    float*  XWb = (float*)(smem + RC_XW);    // stride 68 words

    const int tid  = threadIdx.x;
    const int lane = tid & 31;
    const int wid  = tid >> 5;
    const int slc  = blockIdx.x;         // u-slice
    const int u0   = slc * 16;
    const int m0   = blockIdx.y * 128;
    const int dir  = blockIdx.z;
    const int gi   = blockIdx.y * 2 + blockIdx.z;   // barrier group
    const float* __restrict__ U = dir ? U_b : U_f;

    const int seq = tid & 127;           // CTA-local sequence row (gate math)
    const int uh  = tid >> 7;            // unit-half (0/1)
    const int m   = m0 + seq;

    // ---- one-time: pack resident B (U slice) as fp16, [n][k_perm] ----
    #pragma unroll 4
    for (int it = 0; it < 128; it++) {
        int idx = tid + it * 256;         // 0..32767
        int k = idx >> 6, n = idx & 63;
        float v = U[(size_t)k * GDIM + ((n >> 4) << 9) + u0 + (n & 15)];
        Bs[n * 520 + (k >> 4) * 16 + koff16(k & 15)] = __float2half_rn(v);
    }

    // ---- one-time: mask bits + zero h parity-0 slice ----
    unsigned mbits[4] = {0, 0, 0, 0};
    {
        const int* xr = x + (size_t)m * TLEN;
        for (int t = 0; t < TLEN; t += 4) {
            int4 v = *(const int4*)(xr + t);
            if (v.x) mbits[t >> 5]       |= 1u << (t & 31);
            if (v.y) mbits[(t + 1) >> 5] |= 1u << ((t + 1) & 31);
            if (v.z) mbits[(t + 2) >> 5] |= 1u << ((t + 2) & 31);
            if (v.w) mbits[(t + 3) >> 5] |= 1u << ((t + 3) & 31);
        }
        float4 z4 = make_float4(0.f, 0.f, 0.f, 0.f);
        float4* hp = (float4*)&g_h[0][dir][m][u0 + uh * 8];
        __stcg(hp + 0, z4); __stcg(hp + 1, z4);
    }
    __syncthreads();
    group_sync(gi);

    float cst[8], hst[8];
    #pragma unroll
    for (int i = 0; i < 8; i++) { cst[i] = 0.f; hst[i] = 0.f; }

    const int mb  = (wid >> 1) * 32;     // warp row base
    const int nb  = (wid & 1) * 32;      // warp col base

    // coalesced staging constants: thread covers rows ar0+16i, fixed quad aq
    const int aq    = tid & 15;          // float4 index within 64-float chunk
    const int ar0   = tid >> 4;          // base row
    const int akl   = aq * 4;            // chunk-local k of this thread's quad
    const int apos  = (akl >> 4) * 16 + koff16(akl & 15);   // permuted half-offset

    for (int t = 0; t < TLEN; t++) {
        const int par = t & 1;
        const float* __restrict__ hbase = &g_h[par][dir][m0][0];

        float acc[2][4][4];
        #pragma unroll
        for (int a = 0; a < 2; a++)
            #pragma unroll
            for (int b = 0; b < 4; b++)
                #pragma unroll
                for (int c = 0; c < 4; c++) acc[a][b][c] = 0.0f;

        // prefetch chunk 0 of h: coalesced (warp = 2 rows x 256B)
        float4 pf[8];
        #pragma unroll
        for (int i = 0; i < 8; i++)
            pf[i] = __ldcg((const float4*)(hbase + (size_t)(ar0 + i * 16) * UNITS + akl));

        float4 pfx[8];

        #pragma unroll 1
        for (int cc = 0; cc < 8; cc++) {
            __half* Ab = (__half*)(smem + ((cc & 1) ? RC_A1 : RC_A0));
            // stage prefetched chunk -> A buf (pair-permuted fp16)
            #pragma unroll
            for (int i = 0; i < 8; i++) {
                __half2* dst = (__half2*)&Ab[(ar0 + i * 16) * 68 + apos];
                dst[0] = __floats2half2_rn(pf[i].x, pf[i].y);
                dst[2] = __floats2half2_rn(pf[i].z, pf[i].w);
            }
            __syncthreads();

            if (cc < 7) {                 // prefetch next chunk (overlaps mma)
                #pragma unroll
                for (int i = 0; i < 8; i++)
                    pf[i] = __ldcg((const float4*)(hbase
                              + (size_t)(ar0 + i * 16) * UNITS + (cc + 1) * 64 + akl));
            } else {                      // prefetch xW block: contiguous 32KB
                const float* xwb = g_xW + XW2_BASE(dir, slc, t) + (size_t)m0 * 64;
                #pragma unroll
                for (int i = 0; i < 8; i++)
                    pfx[i] = __ldcs((const float4*)xwb + tid + i * 256);
            }

            #pragma unroll
            for (int j = 0; j < 4; j++) {
                const int q4 = (lane & 3) * 4;
                uint2 av[2][2];
                #pragma unroll
                for (int mt = 0; mt < 2; mt++) {
                    int r = mb + mt * 16 + (lane >> 2);
                    av[mt][0] = *(const uint2*)&Ab[r * 68 + j * 16 + q4];
                    av[mt][1] = *(const uint2*)&Ab[(r + 8) * 68 + j * 16 + q4];
                }
                const int kg = cc * 4 + j;            // global 16-k block
                #pragma unroll
                for (int nt = 0; nt < 4; nt++) {
                    int n = nb + nt * 8 + (lane >> 2);
                    uint2 bb = *(const uint2*)&Bs[n * 520 + kg * 16 + q4];
                    mma16(acc[0][nt], av[0][0].x, av[0][1].x, av[0][0].y, av[0][1].y,
                          bb.x, bb.y);
                    mma16(acc[1][nt], av[1][0].x, av[1][1].x, av[1][0].y, av[1][1].y,
                          bb.x, bb.y);
                }
            }
        }
        __syncthreads();   // all mma done before Z overlays A buffers

        // ---- fragments -> Z smem, and xW block -> XWb (disjoint regions) ----
        #pragma unroll
        for (int mt = 0; mt < 2; mt++) {
            int r = mb + mt * 16 + (lane >> 2);
            #pragma unroll
            for (int nt = 0; nt < 4; nt++) {
                int c = nb + nt * 8 + 2 * (lane & 3);
                *(float2*)&Zs[r * 68 + c]       = make_float2(acc[mt][nt][0], acc[mt][nt][1]);
                *(float2*)&Zs[(r + 8) * 68 + c] = make_float2(acc[mt][nt][2], acc[mt][nt][3]);
            }
        }
        #pragma unroll
        for (int i = 0; i < 8; i++)
            *(float4*)&XWb[(ar0 + i * 16) * 68 + aq * 4] = pfx[i];
        __syncthreads();

        // ---- gate math + masked update (2 threads/seq, 8 units each) ----
        const int  tt = dir ? (TLEN - 1 - t) : t;
        const bool mv = (mbits[tt >> 5] >> (tt & 31)) & 1;

        #pragma unroll
        for (int u = 0; u < 8; u++) hst[u] = hst[u];   // keep regs live

        float zi8[8], zf8[8], zg8[8], zo8[8];
        #pragma unroll
        for (int g = 0; g < 4; g++) {
            float4 hv0 = *(float4*)&Zs[seq * 68 + g * 16 + uh * 8];
            float4 hv1 = *(float4*)&Zs[seq * 68 + g * 16 + uh * 8 + 4];
            float4 xv0 = *(float4*)&XWb[seq * 68 + g * 16 + uh * 8];
            float4 xv1 = *(float4*)&XWb[seq * 68 + g * 16 + uh * 8 + 4];
            float* dst = (g == 0) ? zi8 : (g == 1) ? zf8 : (g == 2) ? zg8 : zo8;
            dst[0] = hv0.x + xv0.x; dst[1] = hv0.y + xv0.y;
            dst[2] = hv0.z + xv0.z; dst[3] = hv0.w + xv0.w;
            dst[4] = hv1.x + xv1.x; dst[5] = hv1.y + xv1.y;
            dst[6] = hv1.z + xv1.z; dst[7] = hv1.w + xv1.w;
        }

        #pragma unroll
        for (int u = 0; u < 8; u++) {
            float ig = fsig(zi8[u]);
            float fg = fsig(zf8[u]);
            float gg = ftanh_(zg8[u]);
            float og = fsig(zo8[u]);
            float cn = fg * cst[u] + ig * gg;
            float hn = og * ftanh_(cn);
            if (mv) { cst[u] = cn; hst[u] = hn; }
        }

        // ---- store h(t+1) ----
        {
            float4* hdst = (float4*)&g_h[par ^ 1][dir][m][u0 + uh * 8];
            __stcg(hdst + 0, make_float4(hst[0], hst[1], hst[2], hst[3]));
            __stcg(hdst + 1, make_float4(hst[4], hst[5], hst[6], hst[7]));
        }
        group_sync(gi);
    }

    // ---- final output ----
    {
        float* op = out + (size_t)m * 1024 + dir * 512 + u0 + uh * 8;
        *(float4*)(op + 0) = make_float4(hst[0], hst[1], hst[2], hst[3]);
        *(float4*)(op + 4) = make_float4(hst[4], hst[5], hst[6], hst[7]);
    }
}

// ===========================================================================
extern "C" void kernel_launch(void* const* d_in, const int* in_sizes, int n_in,
                              void* d_out, int out_size)
{
    const int*   x    = (const int*)  d_in[0];
    const float* emb  = (const float*)d_in[1];
    const float* W_f  = (const float*)d_in[2];
    const float* U_f  = (const float*)d_in[3];
    const float* b_f  = (const float*)d_in[4];
    const float* W_b  = (const float*)d_in[5];
    const float* U_b  = (const float*)d_in[6];
    const float* b_b  = (const float*)d_in[7];
    float* out = (float*)d_out;

    cudaFuncSetAttribute(proj_kernel, cudaFuncAttributeMaxDynamicSharedMemorySize, PJ_SMEM);
    cudaFuncSetAttribute(lstm_kernel, cudaFuncAttributeMaxDynamicSharedMemorySize, RC_SMEM);

    proj_kernel<<<dim3(GDIM / 128, NSEQ, 2), 256, PJ_SMEM>>>(x, emb, W_f, b_f, W_b, b_b);
    lstm_kernel<<<dim3(32, 2, 2), 256, RC_SMEM>>>(x, U_f, U_b, out);
}